// round 10
// baseline (speedup 1.0000x reference)
#include <cuda_runtime.h>
#include <math.h>

// ============================================================================
// FROZEN R9 DESIGN (awaiting first measurement of the R8+R9 fixes).
// R7 evidence: occ=12.4%, issue=22.6%, fma=18.4%, L1=43.5% -> latency-bound.
// R8 fix: M-tile 32, grid (8,32)=256 blocks -> 2 blocks/SM, 4 warps/SMSP.
// R9 fix: fused A-pair LDS.128 (stride 68) -> 2 LDS per k-iter, LDS-issue
//         floor 16 cyc/SMSP/k-iter == fma-pipe time (balanced).
// ============================================================================

#define BN   256   // batch
#define TN   512   // timesteps
#define HN   512   // hidden
#define INP  256   // input dim
#define G4   2048  // 4*HN
#define KC   32    // K-chunk (lstm_step)
#define KCX  16    // K-chunk (xw_gemm)

// Persistent device scratch (no allocation allowed).
__device__ float g_h2[2][BN * HN];   // ping-pong hidden state
__device__ float g_c[BN * HN];       // cell state (in-place safe)
__device__ float g_xW[BN * G4];      // precomputed x0 @ W_w + W_b

__device__ __forceinline__ float sigm(float x) { return 1.0f / (1.0f + expf(-x)); }

// Packed fp32x2 FMA (Blackwell FFMA2): d.lo += a.lo*b.lo, d.hi += a.hi*b.hi
#define FFMA2(d, a, b) \
    asm("fma.rn.f32x2 %0, %1, %2, %0;" : "+l"(d) : "l"(a), "l"(b))

// ---------------------------------------------------------------------------
// One-time: g_xW = x0 @ W_w + W_b      (M=256, K=256, N=2048)
// grid (4, 32), 256 threads, 64x64 tile, 4x4 micro-tile. Runs once; plain fp32.
// ---------------------------------------------------------------------------
__global__ __launch_bounds__(256) void xw_gemm(const float* __restrict__ x0,
                                               const float* __restrict__ Ww,
                                               const float* __restrict__ Wb)
{
    __shared__ float As[KCX][68];
    __shared__ float Bs[KCX][68];

    const int tid = threadIdx.x;
    const int tx = tid & 15, ty = tid >> 4;
    const int m0 = blockIdx.x * 64;
    const int j0 = blockIdx.y * 64;

    const int am = tid >> 2, ak4 = (tid & 3) * 4;   // A loader: 64 rows x 16 k
    const int bk = tid >> 4, bh4 = (tid & 15) * 4;  // B loader: 16 k x 64 cols

    float acc[4][4] = {};

    float4 av = *(const float4*)&x0[(m0 + am) * INP + ak4];
    float4 bv = *(const float4*)&Ww[(size_t)bk * G4 + j0 + bh4];

    for (int kc = 0; kc < INP; kc += KCX) {
        __syncthreads();
        As[ak4 + 0][am] = av.x; As[ak4 + 1][am] = av.y;
        As[ak4 + 2][am] = av.z; As[ak4 + 3][am] = av.w;
        *(float4*)&Bs[bk][bh4] = bv;
        __syncthreads();
        if (kc + KCX < INP) {
            av = *(const float4*)&x0[(m0 + am) * INP + kc + KCX + ak4];
            bv = *(const float4*)&Ww[(size_t)(kc + KCX + bk) * G4 + j0 + bh4];
        }
#pragma unroll
        for (int kk = 0; kk < KCX; kk++) {
            float4 a = *(float4*)&As[kk][ty * 4];
            float4 b = *(float4*)&Bs[kk][tx * 4];
            float ar[4] = {a.x, a.y, a.z, a.w};
            float br[4] = {b.x, b.y, b.z, b.w};
#pragma unroll
            for (int i = 0; i < 4; i++)
#pragma unroll
                for (int j = 0; j < 4; j++) acc[i][j] += ar[i] * br[j];
        }
    }

#pragma unroll
    for (int i = 0; i < 4; i++) {
        int row = ty * 4 + i;
#pragma unroll
        for (int j = 0; j < 4; j++) {
            int c = tx * 4 + j;
            g_xW[(size_t)(m0 + row) * G4 + j0 + c] = acc[i][j] + Wb[j0 + c];
        }
    }
}

// ---------------------------------------------------------------------------
// One fused timestep: gates = g_xW + h_cur @ U_w, LSTM gating, mask, output,
// next-step xcorr drift on h[:, 0:2] folded into the epilogue.
//
// blockIdx.x -> 32 batch rows; blockIdx.y -> 16 hidden cols, covering gate
// columns { q*512 + 16*ny + hh : q in 0..3 } (64 GEMM cols). Micro-tile 2x4.
// A duplicated in smem so one broadcast LDS.128 gives both packed {a,a} pairs.
// Double-buffered k-chunks: one __syncthreads per chunk. Epilogue operands
// prefetched into registers before the final compute.
// ---------------------------------------------------------------------------
__global__ __launch_bounds__(256, 2) void lstm_step(const float* __restrict__ U,
                                                    const int* __restrict__ batch_sizes,
                                                    const float* __restrict__ tau_p,
                                                    float* __restrict__ out,
                                                    int t)
{
    __shared__ __align__(16) float As2[2][KC][68];  // duplicated A: [k][2*row], 32 rows
    __shared__ __align__(16) float Bs[2][KC][68];
    __shared__ __align__(16) float gs[32][68];      // raw gate preactivations (w/o xW)
    __shared__ float hf[32][2];                     // final h ch0/1 (blocks with ny==0)

    const int tid = threadIdx.x;
    const int tx = tid & 15, ty = tid >> 4;         // ty 0..15 -> rows {2ty, 2ty+1}
    const int m0  = blockIdx.x * 32;
    const int hc0 = blockIdx.y * 16;
    const int cur = t & 1;
    const float* __restrict__ hcur = g_h2[cur];
    float* __restrict__ hnext = g_h2[cur ^ 1];

    // Hoisted scalar loads: latency hidden under the GEMM mainloop.
    const int bs = batch_sizes[t];
    const float tau = *tau_p;

    // A loader: 32 rows x 32 k = 1 float4 per thread.
    const int am = tid >> 3, ak4 = (tid & 7) * 4;
    // B loader: 32 k x 64 gate cols = 2 float4 per thread (k rows bkr, bkr+16).
    const int bkr = tid >> 4;
    const int bh4 = (tid & 15) * 4;                       // Bs col 0..60
    const int ucol = (bh4 >> 4) * 512 + hc0 + (bh4 & 15); // gate-structured U col

    unsigned long long acc[2][2] = {};   // packed fp32x2 accumulators (2 rows x 2 col-pairs)

    // --- chunk 0 load + store ---
    float4 av  = *(const float4*)&hcur[(m0 + am) * HN + ak4];
    float4 bv0 = *(const float4*)&U[(size_t)bkr * G4 + ucol];
    float4 bv1 = *(const float4*)&U[(size_t)(bkr + 16) * G4 + ucol];

    {
        *(float2*)&As2[0][ak4 + 0][2 * am] = make_float2(av.x, av.x);
        *(float2*)&As2[0][ak4 + 1][2 * am] = make_float2(av.y, av.y);
        *(float2*)&As2[0][ak4 + 2][2 * am] = make_float2(av.z, av.z);
        *(float2*)&As2[0][ak4 + 3][2 * am] = make_float2(av.w, av.w);
        *(float4*)&Bs[0][bkr][bh4]      = bv0;
        *(float4*)&Bs[0][bkr + 16][bh4] = bv1;
    }
    __syncthreads();

    auto compute = [&](int pp) {
#pragma unroll
        for (int kk = 0; kk < KC; kk++) {
            ulonglong2 b01 = *(const ulonglong2*)&Bs[pp][kk][tx * 4];
            // One LDS.128: {row 2ty dup, row 2ty+1 dup} adjacent packed pairs.
            // 16B-aligned for all kk: (kk*68 + 4*ty)*4 = 272*kk + 16*ty.
            ulonglong2 a01 = *(const ulonglong2*)&As2[pp][kk][4 * ty];
            FFMA2(acc[0][0], a01.x, b01.x); FFMA2(acc[0][1], a01.x, b01.y);
            FFMA2(acc[1][0], a01.y, b01.x); FFMA2(acc[1][1], a01.y, b01.y);
        }
    };

    int p = 0;
    for (int kc = KC; kc < HN; kc += KC) {
        // prefetch next k-chunk from global
        av  = *(const float4*)&hcur[(m0 + am) * HN + kc + ak4];
        bv0 = *(const float4*)&U[(size_t)(kc + bkr) * G4 + ucol];
        bv1 = *(const float4*)&U[(size_t)(kc + bkr + 16) * G4 + ucol];

        compute(p);

        int q = p ^ 1;
        *(float2*)&As2[q][ak4 + 0][2 * am] = make_float2(av.x, av.x);
        *(float2*)&As2[q][ak4 + 1][2 * am] = make_float2(av.y, av.y);
        *(float2*)&As2[q][ak4 + 2][2 * am] = make_float2(av.z, av.z);
        *(float2*)&As2[q][ak4 + 3][2 * am] = make_float2(av.w, av.w);
        *(float4*)&Bs[q][bkr][bh4]      = bv0;
        *(float4*)&Bs[q][bkr + 16][bh4] = bv1;
        __syncthreads();
        p = q;
    }

    // Prefetch epilogue operands into registers BEFORE the final compute:
    // g_xW / hcur read-only this step; g_c[b,hidx] read+written by this thread
    // only. 12 independent LDGs hidden under the last chunk's FFMA2 work.
    float xwi[2], xwf[2], xwg[2], xwo[2], coldp[2], holdp[2];
#pragma unroll
    for (int r = 0; r < 2; r++) {
        int e = tid + 256 * r;          // 0..511 : 32 rows x 16 hidden cols
        int row = e >> 4, hh = e & 15;
        int b = m0 + row;
        int hidx = hc0 + hh;
        size_t xb = (size_t)b * G4;
        xwi[r]   = g_xW[xb + 0 * 512 + hidx];
        xwf[r]   = g_xW[xb + 1 * 512 + hidx];
        xwg[r]   = g_xW[xb + 2 * 512 + hidx];
        xwo[r]   = g_xW[xb + 3 * 512 + hidx];
        coldp[r] = g_c[b * HN + hidx];
        holdp[r] = hcur[b * HN + hidx];
    }

    compute(p);

    // Exchange: store packed fp32x2 accumulators directly (STS.64).
    // gs row stride = 68 floats = 272 B (16B-aligned); col = tx*4 + 2*jp -> 8B-aligned.
#pragma unroll
    for (int i = 0; i < 2; i++) {
        int row = 2 * ty + i;
#pragma unroll
        for (int jp = 0; jp < 2; jp++) {
            *(unsigned long long*)&gs[row][tx * 4 + 2 * jp] = acc[i][jp];
        }
    }
    __syncthreads();

#pragma unroll
    for (int r = 0; r < 2; r++) {
        int e = tid + 256 * r;
        int row = e >> 4, hh = e & 15;
        int b = m0 + row;
        int hidx = hc0 + hh;

        float iv = gs[row][hh]      + xwi[r];
        float fv = gs[row][16 + hh] + xwf[r];
        float gv = gs[row][32 + hh] + xwg[r];
        float ov = gs[row][48 + hh] + xwo[r];

        float cn = sigm(fv) * coldp[r] + sigm(iv) * tanhf(gv);
        float hn = sigm(ov) * tanhf(cn);

        bool msk = b < bs;
        float hfin = msk ? hn : holdp[r];

        if (msk) g_c[b * HN + hidx] = cn;
        out[(size_t)t * (BN * HN) + (size_t)b * HN + hidx] = msk ? hn : 0.0f;

        if (blockIdx.y == 0 && hh < 2) {
            hf[row][hh] = hfin;          // deferred: xcorr applied below
        } else {
            hnext[b * HN + hidx] = hfin;
        }
    }

    if (blockIdx.y == 0) {
        __syncthreads();                 // block-uniform branch: safe
        if (tid < 32) {
            int b = m0 + tid;
            // Fold next step's xcorr drift (reference applies it at step start,
            // t != 0, to ALL rows). Skip after the final step so returned h matches.
            float taue = (t == TN - 1) ? 0.0f : tau;
            float h0v = hf[tid][0], h1v = hf[tid][1];
            hnext[b * HN + 0] = h0v + taue * (1.5f * h0v + h1v * (1.0f / 1.5f));
            hnext[b * HN + 1] = h1v + taue * (-1.5f * h0v);
        }
    }
}

// ---------------------------------------------------------------------------
// Inputs (metadata order): rnn_input_data, batch_sizes, h0, c0, tau, W_w, W_b, U_w
// Output: concat( outputs[T,B,H], h[1,B,H], c[1,B,H] )  as float32
// ---------------------------------------------------------------------------
extern "C" void kernel_launch(void* const* d_in, const int* in_sizes, int n_in,
                              void* d_out, int out_size)
{
    (void)in_sizes; (void)n_in; (void)out_size;

    const float* x_in = (const float*)d_in[0];   // rnn_input_data (B*T, I); only first B rows used
    const int*   bsz  = (const int*)d_in[1];     // batch_sizes (T,)
    const float* h0   = (const float*)d_in[2];   // (1,B,H)
    const float* c0   = (const float*)d_in[3];   // (1,B,H)
    const float* tau  = (const float*)d_in[4];   // scalar
    const float* Ww   = (const float*)d_in[5];   // (I, 4H)
    const float* Wb   = (const float*)d_in[6];   // (4H,)
    const float* Uw   = (const float*)d_in[7];   // (H, 4H)
    float* out = (float*)d_out;

    // Encourage 2 blocks/SM for lstm_step (smem 43.8KB/block -> 87.5KB/SM).
    cudaFuncSetAttribute(lstm_step,
                         cudaFuncAttributePreferredSharedMemoryCarveout, 100);

    void *hAddr = nullptr, *cAddr = nullptr;
    cudaGetSymbolAddress(&hAddr, g_h2);
    cudaGetSymbolAddress(&cAddr, g_c);

    // Init state: h -> ping buffer 0 (t=0 reads buf[t&1]=0), c in place.
    cudaMemcpyAsync(hAddr, h0, (size_t)BN * HN * sizeof(float),
                    cudaMemcpyDeviceToDevice, 0);
    cudaMemcpyAsync(cAddr, c0, (size_t)BN * HN * sizeof(float),
                    cudaMemcpyDeviceToDevice, 0);

    xw_gemm<<<dim3(4, 32), 256>>>(x_in, Ww, Wb);

    dim3 grid(8, 32);
    for (int t = 0; t < TN; t++)
        lstm_step<<<grid, 256>>>(Uw, bsz, tau, out, t);

    // Final h lives in buffer (TN & 1) = 0, i.e. the base of g_h2.
    cudaMemcpyAsync(out + (size_t)TN * BN * HN, hAddr,
                    (size_t)BN * HN * sizeof(float), cudaMemcpyDeviceToDevice, 0);
    cudaMemcpyAsync(out + (size_t)TN * BN * HN + (size_t)BN * HN, cAddr,
                    (size_t)BN * HN * sizeof(float), cudaMemcpyDeviceToDevice, 0);
}